// round 1
// baseline (speedup 1.0000x reference)
#include <cuda_runtime.h>
#include <math.h>

#define T_LEN   2048
#define TMASK   2047
#define NKEEP   1536
#define EDGE    256
#define NBC     16
#define NBAND   80
#define PHA_NB  50
#define AMP_NB  30
#define NBINS   18
#define NK      641     // bins k = 0..640 cover all bands (max khi = 634)
#define TPER    6       // t-values per thread in synth (256 threads * 6 = 1536)

// ---------------- scratch (device globals; no allocations allowed) ----------
__device__ float2        g_tw[T_LEN];                  // e^{+2*pi*i*j/T}
__device__ int           g_klo[NBAND];
__device__ int           g_khi[NBAND];
__device__ float2        g_Xf[NBC][NK];                // DFT bins
__device__ unsigned char g_pidx[NBC][PHA_NB][NKEEP];   // phase bin index
__device__ float         g_amp[NBC][NKEEP][AMP_NB];    // amplitude, t-major

// ---------------- init: twiddle table + band bin ranges ---------------------
__global__ void init_kernel() {
    int tid = threadIdx.x;
    for (int j = tid; j < T_LEN; j += blockDim.x) {
        double a = (2.0 * M_PI / (double)T_LEN) * (double)j;
        double s, c;
        sincos(a, &s, &c);
        g_tw[j] = make_float2((float)c, (float)s);
    }
    if (tid < NBAND) {
        // replicate numpy: linspace in double (mul then add, no fma), *factor
        // in double, cast to float32, then fp32 comparisons vs k*0.25
        double lo_d, hi_d;
        if (tid < PHA_NB) {
            double step = 18.0 / 49.0;                       // (20-2)/49
            double mid  = (tid == PHA_NB - 1) ? 20.0
                        : __dadd_rn(__dmul_rn((double)tid, step), 2.0);
            lo_d = __dmul_rn(mid, 0.75);
            hi_d = __dmul_rn(mid, 1.25);
        } else {
            int i = tid - PHA_NB;
            double ae = 256.0 / 1.8 - 1.0;                   // 141.222...
            if (ae > 160.0) ae = 160.0;
            ae = (double)(int)ae;                            // 141.0
            double step = __ddiv_rn(__dsub_rn(ae, 60.0), 29.0);
            double mid  = (i == AMP_NB - 1) ? ae
                        : __dadd_rn(__dmul_rn((double)i, step), 60.0);
            lo_d = __dmul_rn(mid, 0.875);
            hi_d = __dmul_rn(mid, 1.125);
        }
        float lo = (float)lo_d, hi = (float)hi_d;
        int klo = -1, khi = -2;
        for (int k = 1; k <= 1024; k++) {
            float f = (float)k * 0.25f;                      // exact in fp32
            if (f >= lo && f <= hi) { if (klo < 0) klo = k; khi = k; }
        }
        g_klo[tid] = klo;
        g_khi[tid] = khi;
    }
}

// ---------------- kernel 1: DFT bins 0..640 (Kahan fp32) --------------------
// grid (41, 16), block 256: 16 bins/block x 16 t-slices/bin, 128 t per thread
__global__ __launch_bounds__(256) void dft_kernel(const float* __restrict__ x) {
    __shared__ float2 s_tw[T_LEN];
    __shared__ float  s_x[T_LEN];
    int bc  = blockIdx.y;
    int tid = threadIdx.x;
    for (int j = tid; j < T_LEN; j += 256) {
        s_tw[j] = g_tw[j];
        s_x[j]  = x[bc * T_LEN + j];
    }
    __syncthreads();

    int bl = tid >> 4;        // bin within block
    int sl = tid & 15;        // t-slice
    int k  = blockIdx.x * 16 + bl;

    float sre = 0.f, cre = 0.f, sim = 0.f, cim = 0.f;  // Kahan sums
    if (k < NK) {
        for (int i = 0; i < 128; i++) {
            int t  = sl + (i << 4);
            int id = (k * t) & TMASK;
            float2 w = s_tw[id];
            float  xv = s_x[t];
            float pr =  xv * w.x;                      // e^{-i...}: conj table
            float pi = -xv * w.y;
            float y, tt;
            y = pr - cre; tt = sre + y; cre = (tt - sre) - y; sre = tt;
            y = pi - cim; tt = sim + y; cim = (tt - sim) - y; sim = tt;
        }
    }
    // reduce 16 slices (lanes sl=0..15 within each 16-lane group)
    for (int off = 8; off; off >>= 1) {
        sre += __shfl_xor_sync(0xffffffffu, sre, off);
        sim += __shfl_xor_sync(0xffffffffu, sim, off);
    }
    if (sl == 0 && k < NK) g_Xf[bc][k] = make_float2(sre, sim);
}

// ---------------- kernel 2: band synthesis + angle/abs ----------------------
// grid (80, 16), block 256; each thread owns 6 t-values with their own
// twiddle recurrence, re-synced from the exact table every 8 bins.
__global__ __launch_bounds__(256) void synth_kernel() {
    __shared__ float2 s_tw[T_LEN];
    __shared__ float2 s_Xf[160];     // max bins per band = 141
    int band = blockIdx.x;
    int bc   = blockIdx.y;
    int tid  = threadIdx.x;
    int klo  = g_klo[band];
    int khi  = g_khi[band];
    int nb   = khi - klo + 1;

    for (int j = tid; j < T_LEN; j += 256) s_tw[j] = g_tw[j];
    for (int j = tid; j < nb;    j += 256) s_Xf[j] = g_Xf[bc][klo + j];
    __syncthreads();

    float ar[TPER], ai[TPER], zr[TPER], zi[TPER], wr[TPER], wi[TPER];
    int   tq[TPER];
#pragma unroll
    for (int j = 0; j < TPER; j++) {
        int t = EDGE + tid + j * 256;
        tq[j] = t;
        float2 w = s_tw[t];          // step e^{2*pi*i*t/T}
        wr[j] = w.x; wi[j] = w.y;
        ar[j] = 0.f; ai[j] = 0.f;
    }

    for (int kk = 0; kk < nb; kk += 8) {
        // exact re-sync of the rotators from the table
#pragma unroll
        for (int j = 0; j < TPER; j++) {
            int id = ((klo + kk) * tq[j]) & TMASK;
            float2 z = s_tw[id];
            zr[j] = z.x; zi[j] = z.y;
        }
        int kend = min(kk + 8, nb);
        for (int k2 = kk; k2 < kend; k2++) {
            float2 X = s_Xf[k2];
#pragma unroll
            for (int j = 0; j < TPER; j++) {
                ar[j] += X.x * zr[j] - X.y * zi[j];
                ai[j] += X.x * zi[j] + X.y * zr[j];
                float nzr = zr[j] * wr[j] - zi[j] * wi[j];
                float nzi = zr[j] * wi[j] + zi[j] * wr[j];
                zr[j] = nzr; zi[j] = nzi;
            }
        }
    }

    if (band < PHA_NB) {
        const float PIF    = 3.14159274101257324f;           // (float)pi
        const float WIDTHF = (float)(2.0 * M_PI / (double)NBINS);
#pragma unroll
        for (int j = 0; j < TPER; j++) {
            float ang = atan2f(ai[j], ar[j]);
            float q   = __fdiv_rn(ang + PIF, WIDTHF);        // match ref divide
            int   idx = (int)floorf(q);
            idx = max(0, min(idx, NBINS - 1));
            g_pidx[bc][band][tq[j] - EDGE] = (unsigned char)idx;
        }
    } else {
        int a = band - PHA_NB;
#pragma unroll
        for (int j = 0; j < TPER; j++) {
            g_amp[bc][tq[j] - EDGE][a] = sqrtf(ar[j] * ar[j] + ai[j] * ai[j]);
        }
    }
}

// ---------------- kernel 3: binned means + MI --------------------------------
// grid (50, 16), block 128 (4 warps). Lane = amp index (0..29), lane30 = count.
// Run-length compaction: phase bin changes slowly -> flush shared RMW rarely.
__global__ __launch_bounds__(128) void mi_kernel(float* __restrict__ out) {
    __shared__ unsigned int s_idx32[NKEEP / 4];
    __shared__ float s_acc[4][NBINS][32];
    int bc   = blockIdx.y;
    int p    = blockIdx.x;
    int tid  = threadIdx.x;
    int w    = tid >> 5;
    int lane = tid & 31;

    const unsigned int* src =
        (const unsigned int*)&g_pidx[bc][p][0];
    for (int j = tid; j < NKEEP / 4; j += 128) s_idx32[j] = src[j];
    for (int j = tid; j < 4 * NBINS * 32; j += 128) ((float*)s_acc)[j] = 0.f;
    __syncthreads();

    const unsigned char* s_idx = (const unsigned char*)s_idx32;
    int t0 = w * (NKEEP / 4);
    int t1 = t0 + (NKEEP / 4);
    int kprev = -1;
    float run = 0.f;
    for (int t = t0; t < t1; t++) {
        int k = s_idx[t];                       // uniform across warp
        float v;
        if (lane < AMP_NB)      v = g_amp[bc][t][lane];
        else if (lane == AMP_NB) v = 1.0f;      // count channel
        else                     v = 0.0f;
        if (k != kprev) {
            if (kprev >= 0) s_acc[w][kprev][lane] += run;
            kprev = k; run = v;
        } else {
            run += v;
        }
    }
    if (kprev >= 0) s_acc[w][kprev][lane] += run;
    __syncthreads();

    if (tid < AMP_NB) {
        float means[NBINS];
        float tot = 0.f;
#pragma unroll
        for (int k = 0; k < NBINS; k++) {
            float cnt = s_acc[0][k][AMP_NB] + s_acc[1][k][AMP_NB]
                      + s_acc[2][k][AMP_NB] + s_acc[3][k][AMP_NB];
            float s   = s_acc[0][k][tid] + s_acc[1][k][tid]
                      + s_acc[2][k][tid] + s_acc[3][k][tid];
            float m   = __fdiv_rn(s, fmaxf(cnt, 1e-9f));
            means[k]  = m;
            tot      += m;
        }
        float denom = fmaxf(tot, 1e-9f);
        float acc = 0.f;
#pragma unroll
        for (int k = 0; k < NBINS; k++) {
            float pr = __fdiv_rn(means[k], denom);
            acc += pr * logf(pr + 1e-9f);
        }
        const float LOG_NB = 2.8903717578961645f;   // log(18)
        out[(bc * PHA_NB + p) * AMP_NB + tid] = (LOG_NB + acc) / LOG_NB;
    }
}

// ---------------- launch -----------------------------------------------------
extern "C" void kernel_launch(void* const* d_in, const int* in_sizes, int n_in,
                              void* d_out, int out_size) {
    const float* x = (const float*)d_in[0];
    float* out = (float*)d_out;

    init_kernel<<<1, 256>>>();
    dft_kernel<<<dim3((NK + 15) / 16, NBC), 256>>>(x);
    synth_kernel<<<dim3(NBAND, NBC), 256>>>();
    mi_kernel<<<dim3(PHA_NB, NBC), 128>>>(out);
}

// round 2
// speedup vs baseline: 1.4610x; 1.4610x over previous
#include <cuda_runtime.h>
#include <math.h>

#define T_LEN   2048
#define TMASK   2047
#define NKEEP   1536
#define EDGE    256
#define NBC     16
#define NBAND   80
#define PHA_NB  50
#define AMP_NB  30
#define NBINS   18
#define NK      641     // DFT bins 0..640 cover all bands (max khi = 634)
#define NEV     160     // 2 prefix boundaries per band
#define PTILE   2       // p's per mi block

// ---------------- scratch (device globals; no allocations allowed) ----------
__device__ float2        g_tw[T_LEN];                  // e^{+2*pi*i*j/T}
__device__ int           g_klo[NBAND];
__device__ int           g_khi[NBAND];
__device__ int           g_evk[NEV + 1];               // sorted event k's
__device__ int           g_evslot[NEV];                // slot = 2*band + type
__device__ float2        g_Xf[NBC][NK];                // DFT bins
__device__ float2        g_pref[NBC][NEV][NKEEP];      // prefix snapshots
__device__ unsigned char g_pidx[NBC][PHA_NB][NKEEP];   // phase bin index
__device__ float         g_amp[NBC][NKEEP][AMP_NB];    // amplitude, t-major

// ---------------- init: twiddles + band ranges + sorted event list ----------
__global__ void init_kernel() {
    __shared__ int s_key[NEV];
    int tid = threadIdx.x;
    for (int j = tid; j < T_LEN; j += blockDim.x) {
        float s, c;
        sincospif((float)j * (1.0f / 1024.0f), &s, &c);   // 2*pi*j/2048 exact
        g_tw[j] = make_float2(c, s);
    }
    if (tid < NBAND) {
        // replicate numpy double-precision linspace, then fp32 comparisons
        double lo_d, hi_d;
        if (tid < PHA_NB) {
            double step = 18.0 / 49.0;
            double mid  = (tid == PHA_NB - 1) ? 20.0
                        : __dadd_rn(__dmul_rn((double)tid, step), 2.0);
            lo_d = __dmul_rn(mid, 0.75);
            hi_d = __dmul_rn(mid, 1.25);
        } else {
            int i = tid - PHA_NB;
            double ae = 256.0 / 1.8 - 1.0;
            if (ae > 160.0) ae = 160.0;
            ae = (double)(int)ae;                         // 141.0
            double step = __ddiv_rn(__dsub_rn(ae, 60.0), 29.0);
            double mid  = (i == AMP_NB - 1) ? ae
                        : __dadd_rn(__dmul_rn((double)i, step), 60.0);
            lo_d = __dmul_rn(mid, 0.875);
            hi_d = __dmul_rn(mid, 1.125);
        }
        float lo = (float)lo_d, hi = (float)hi_d;
        int klo = -1, khi = -2;
        for (int k = 1; k < NK; k++) {
            float f = (float)k * 0.25f;                   // exact in fp32
            if (f >= lo && f <= hi) { if (klo < 0) klo = k; khi = k; }
        }
        g_klo[tid] = klo;
        g_khi[tid] = khi;
    }
    __syncthreads();
    if (tid < NEV) {
        int b = tid >> 1, type = tid & 1;
        s_key[tid] = type ? g_khi[b] : (g_klo[b] - 1);
    }
    __syncthreads();
    if (tid < NEV) {
        int key = s_key[tid];
        int rank = 0;
        for (int j = 0; j < NEV; j++)
            rank += (s_key[j] < key) || (s_key[j] == key && j < tid);
        g_evk[rank]   = key;
        g_evslot[rank] = tid;                             // slot == 2b+type
    }
    if (tid == 0) g_evk[NEV] = 1 << 30;                   // sentinel
}

// ---------------- kernel 1: DFT bins 0..640 (plain fp32) --------------------
// grid (41, 16), block 256: 16 bins/block x 16 t-slices/bin, 128 t per thread
__global__ __launch_bounds__(256) void dft_kernel(const float* __restrict__ x) {
    __shared__ float2 s_tw[T_LEN];
    __shared__ float  s_x[T_LEN];
    int bc  = blockIdx.y;
    int tid = threadIdx.x;
    for (int j = tid; j < T_LEN; j += 256) {
        s_tw[j] = g_tw[j];
        s_x[j]  = x[bc * T_LEN + j];
    }
    __syncthreads();

    int bl = tid >> 4;        // bin within block
    int sl = tid & 15;        // t-slice (consecutive lanes -> consecutive t)
    int k  = blockIdx.x * 16 + bl;

    float sre = 0.f, sim2 = 0.f;
    if (k < NK) {
#pragma unroll 4
        for (int i = 0; i < 128; i++) {
            int t  = sl + (i << 4);
            int id = (k * t) & TMASK;
            float2 w = s_tw[id];
            float  xv = s_x[t];
            sre  = fmaf(xv, w.x, sre);
            sim2 = fmaf(xv, w.y, sim2);     // negate once at the end
        }
    }
    for (int off = 8; off; off >>= 1) {
        sre  += __shfl_xor_sync(0xffffffffu, sre, off);
        sim2 += __shfl_xor_sync(0xffffffffu, sim2, off);
    }
    if (sl == 0 && k < NK) g_Xf[bc][k] = make_float2(sre, -sim2);
}

// ---------------- kernel 2: prefix sweep over k + fused band tail -----------
// grid (12, 16), block 128; one thread per kept t. Serial sweep k = 0..639
// maintains the running prefix of X[k]*e^{i*w*k*t}; at each band boundary it
// snapshots to g_pref. Tail converts P(khi)-P(klo-1) to phase bins / amps.
__global__ __launch_bounds__(128) void prefix_kernel() {
    __shared__ float2 s_tw[T_LEN];
    __shared__ float2 s_Xf[NK];
    __shared__ int    s_evk[NEV + 1];
    __shared__ int    s_evslot[NEV];
    int bc  = blockIdx.y;
    int tid = threadIdx.x;
    for (int j = tid; j < T_LEN; j += 128) s_tw[j] = g_tw[j];
    for (int j = tid; j < NK;    j += 128) s_Xf[j] = g_Xf[bc][j];
    for (int j = tid; j < NEV;   j += 128) { s_evk[j] = g_evk[j]; s_evslot[j] = g_evslot[j]; }
    if (tid == 0) s_evk[NEV] = 1 << 30;
    __syncthreads();

    int tk = blockIdx.x * 128 + tid;      // 0..1535
    int t  = EDGE + tk;
    float2 w = s_tw[t];                   // step e^{i*w*t} per k increment
    float S1r = 0.f, S2r = 0.f, S1i = 0.f, S2i = 0.f;   // coarse sums
    float c1r = 0.f, c2r = 0.f, c1i = 0.f, c2i = 0.f;   // chunk-of-16 sums
    float zr = 1.f, zi = 0.f;
    int   j = 0;
    int   nev = s_evk[0];

#pragma unroll 16
    for (int k = 0; k < 640; k++) {
        if ((k & 15) == 1) {              // exact re-sync; odd stride -> no LDS conflict
            float2 z = s_tw[(k * t) & TMASK];
            zr = z.x; zi = z.y;
        }
        float2 X = s_Xf[k];
        c1r = fmaf(X.x, zr, c1r);
        c2r = fmaf(X.y, zi, c2r);
        c1i = fmaf(X.x, zi, c1i);
        c2i = fmaf(X.y, zr, c2i);
        while (k == nev) {                // uniform across warp
            int slot = s_evslot[j];
            float vr = (S1r + c1r) - (S2r + c2r);
            float vi = (S1i + c1i) + (S2i + c2i);
            g_pref[bc][slot][tk] = make_float2(vr, vi);
            j++;
            nev = s_evk[j];
        }
        if ((k & 15) == 15) {
            S1r += c1r; S2r += c2r; S1i += c1i; S2i += c2i;
            c1r = 0.f; c2r = 0.f; c1i = 0.f; c2i = 0.f;
        }
        float nzr = zr * w.x - zi * w.y;
        float nzi = zr * w.y + zi * w.x;
        zr = nzr; zi = nzi;
    }

    // tail: band values from prefix differences (same-thread read-after-write)
    const float PIF    = 3.14159274101257324f;
    const float WIDTHF = (float)(2.0 * M_PI / (double)NBINS);
    for (int b = 0; b < NBAND; b++) {
        float2 pa = g_pref[bc][2 * b][tk];
        float2 pb = g_pref[bc][2 * b + 1][tk];
        float re = pb.x - pa.x;
        float im = pb.y - pa.y;
        if (b < PHA_NB) {
            float ang = atan2f(im, re);
            float q   = __fdiv_rn(ang + PIF, WIDTHF);
            int   idx = (int)floorf(q);
            idx = max(0, min(idx, NBINS - 1));
            g_pidx[bc][b][tk] = (unsigned char)idx;
        } else {
            g_amp[bc][tk][b - PHA_NB] = sqrtf(re * re + im * im);
        }
    }
}

// ---------------- kernel 3: binned means + MI --------------------------------
// grid (25, 16), block 256 (8 warps), 2 p's per block (amp traffic halved).
// Lane = amp index (0..29), lane 30 = count channel. Branch-free chunks of 4 t.
__global__ __launch_bounds__(256) void mi_kernel(float* __restrict__ out) {
    __shared__ unsigned int s_idxw[PTILE][NKEEP / 4];
    __shared__ float s_acc[PTILE][8][NBINS][32];          // 36.9 KB
    int bc   = blockIdx.y;
    int p0   = blockIdx.x * PTILE;
    int tid  = threadIdx.x;
    int w    = tid >> 5;
    int lane = tid & 31;

    for (int pp = 0; pp < PTILE; pp++) {
        const unsigned int* src = (const unsigned int*)&g_pidx[bc][p0 + pp][0];
        for (int j = tid; j < NKEEP / 4; j += 256) s_idxw[pp][j] = src[j];
    }
    for (int j = tid; j < PTILE * 8 * NBINS * 32; j += 256)
        ((float*)s_acc)[j] = 0.f;
    __syncthreads();

    const float* amp = &g_amp[bc][0][0];
    int  t0    = w * (NKEEP / 8);         // 192 t per warp
    bool isamp = lane < AMP_NB;
    float vconst = (lane == AMP_NB) ? 1.0f : 0.0f;

    for (int c = 0; c < (NKEEP / 8) / 4; c++) {
        int t = t0 + c * 4;
        float v0, v1, v2, v3;
        if (isamp) {
            v0 = amp[(t + 0) * AMP_NB + lane];
            v1 = amp[(t + 1) * AMP_NB + lane];
            v2 = amp[(t + 2) * AMP_NB + lane];
            v3 = amp[(t + 3) * AMP_NB + lane];
        } else {
            v0 = v1 = v2 = v3 = vconst;
        }
#pragma unroll
        for (int pp = 0; pp < PTILE; pp++) {
            unsigned int word = s_idxw[pp][t >> 2];
            s_acc[pp][w][word & 255][lane]         += v0;
            s_acc[pp][w][(word >> 8) & 255][lane]  += v1;
            s_acc[pp][w][(word >> 16) & 255][lane] += v2;
            s_acc[pp][w][word >> 24][lane]         += v3;
        }
    }
    __syncthreads();

    if (tid < AMP_NB) {
        const float LOG_NB = 2.8903717578961645f;          // log(18)
        for (int pp = 0; pp < PTILE; pp++) {
            float means[NBINS];
            float tot = 0.f;
#pragma unroll
            for (int k = 0; k < NBINS; k++) {
                float cnt = 0.f, s = 0.f;
#pragma unroll
                for (int w8 = 0; w8 < 8; w8++) {
                    cnt += s_acc[pp][w8][k][AMP_NB];
                    s   += s_acc[pp][w8][k][tid];
                }
                float m = __fdiv_rn(s, fmaxf(cnt, 1e-9f));
                means[k] = m;
                tot += m;
            }
            float denom = fmaxf(tot, 1e-9f);
            float acc = 0.f;
#pragma unroll
            for (int k = 0; k < NBINS; k++) {
                float pr = __fdiv_rn(means[k], denom);
                acc += pr * logf(pr + 1e-9f);
            }
            out[(bc * PHA_NB + p0 + pp) * AMP_NB + tid] = (LOG_NB + acc) / LOG_NB;
        }
    }
}

// ---------------- launch -----------------------------------------------------
extern "C" void kernel_launch(void* const* d_in, const int* in_sizes, int n_in,
                              void* d_out, int out_size) {
    const float* x = (const float*)d_in[0];
    float* out = (float*)d_out;

    init_kernel<<<1, 256>>>();
    dft_kernel<<<dim3((NK + 15) / 16, NBC), 256>>>(x);
    prefix_kernel<<<dim3(NKEEP / 128, NBC), 128>>>();
    mi_kernel<<<dim3(PHA_NB / PTILE, NBC), 256>>>(out);
}